// round 3
// baseline (speedup 1.0000x reference)
#include <cuda_runtime.h>
#include <cstdint>
#include <cstddef>

#define HID     64
#define DIMH    128
#define DIMU    256
#define ROWS    16
#define NWARP   8
#define THREADS 256
#define JPW     8     // j-columns per jgroup
#define NG      16    // jgroups: g = 2*w + (lane>>4); 16 x 8 = 128 j-columns
#define WPAD    132   // padded row length (floats): conflict-free stride, 16B-aligned

struct Smem {
  float hs[ROWS][WPAD];        // h tile
  float Wc[2 * HID][WPAD];     // rows 0..63: W1u[:,1:], rows 64..127: W1p[:,2:]
  float cu[HID], cp0[HID], cp1[HID];
  float b1u[HID], b1p[HID], W2u[HID], W2p[HID];
  float cnt_n1[ROWS], cnt01[ROWS], cnt10[ROWS], cnt11[ROWS];
  float partial[NG][ROWS];
};

__device__ __forceinline__ float gelu_f(float x) {
  // exact erf-based GELU (matches torch nn.GELU default / jax approximate=False)
  return 0.5f * x * (1.0f + erff(x * 0.7071067811865476f));
}

extern __shared__ __align__(16) float smem_raw[];

__global__ void __launch_bounds__(THREADS) fem_kernel(
    const float* __restrict__ u,   const float* __restrict__ h,
    const float* __restrict__ W1u, const float* __restrict__ b1u,
    const float* __restrict__ W2u, const float* __restrict__ b2u,
    const float* __restrict__ W1p, const float* __restrict__ b1p,
    const float* __restrict__ W2p, const float* __restrict__ b2p,
    float* __restrict__ out)
{
  Smem* s = reinterpret_cast<Smem*>(smem_raw);
  const int tid  = threadIdx.x;
  const int lane = tid & 31;
  const int w    = tid >> 5;
  const int r0   = blockIdx.x * ROWS;

  // ---- load h tile [16 x 128] (coalesced float4) ----
  {
    const float4* h4 = reinterpret_cast<const float4*>(h) + (size_t)r0 * (DIMH / 4);
    for (int i = tid; i < ROWS * (DIMH / 4); i += THREADS) {
      float4 v = h4[i];
      int row = i >> 5, c4 = i & 31;
      *reinterpret_cast<float4*>(&s->hs[row][c4 * 4]) = v;
    }
  }
  // ---- load W1u [64 x 129]: col 0 -> cu, cols 1.. -> Wc[j] ----
  for (int i = tid; i < HID * 129; i += THREADS) {
    int j = i / 129, c = i - j * 129;
    float v = W1u[i];
    if (c == 0) s->cu[j] = v;
    else        s->Wc[j][c - 1] = v;
  }
  // ---- load W1p [64 x 130]: cols 0,1 -> cp0,cp1, cols 2.. -> Wc[64+j] ----
  for (int i = tid; i < HID * 130; i += THREADS) {
    int j = i / 130, c = i - j * 130;
    float v = W1p[i];
    if (c == 0)      s->cp0[j] = v;
    else if (c == 1) s->cp1[j] = v;
    else             s->Wc[HID + j][c - 2] = v;
  }
  if (tid < HID) {
    s->b1u[tid] = b1u[tid];
    s->b1p[tid] = b1p[tid];
    s->W2u[tid] = W2u[tid];
    s->W2p[tid] = W2p[tid];
  }

  // ---- count u bits per row: n1 and consecutive-pair class counts ----
  // warp w handles rows w, w+8. lane covers elems [4*lane..4*lane+3]
  // in each half of the 256-wide row (two float4 loads).
  {
    const float4* u4 = reinterpret_cast<const float4*>(u);
    for (int rr = w; rr < ROWS; rr += NWARP) {
      size_t base = (size_t)(r0 + rr) * (DIMU / 4);
      float4 a = u4[base + lane];        // elems 4l .. 4l+3
      float4 b = u4[base + 32 + lane];   // elems 128+4l .. 128+4l+3
      int a0 = a.x > 0.5f, a1 = a.y > 0.5f, a2 = a.z > 0.5f, a3 = a.w > 0.5f;
      int e0 = b.x > 0.5f, e1 = b.y > 0.5f, e2 = b.z > 0.5f, e3 = b.w > 0.5f;
      int n1 = a0 + a1 + a2 + a3 + e0 + e1 + e2 + e3;
      const unsigned F = 0xffffffffu;
      int a0n  = __shfl_down_sync(F, a0, 1);  // next lane's a0
      int e0n  = __shfl_down_sync(F, e0, 1);  // next lane's b0
      int e0l0 = __shfl_sync(F, e0, 0);       // lane0's b0 == element 128
      int c11 = 0, c10 = 0, c01 = 0;
#define ADDP(X, Y) { c11 += (X) & (Y); c10 += (X) & (1 ^ (Y)); c01 += (1 ^ (X)) & (Y); }
      ADDP(a0, a1) ADDP(a1, a2) ADDP(a2, a3)
      int xa = (lane < 31) ? a0n : e0l0;      // pair (4l+3, 4l+4); lane31 -> (127,128)
      ADDP(a3, xa)
      ADDP(e0, e1) ADDP(e1, e2) ADDP(e2, e3)
      if (lane < 31) ADDP(e3, e0n)            // lane31's (255,256) doesn't exist
#undef ADDP
      n1  = __reduce_add_sync(F, n1);
      c11 = __reduce_add_sync(F, c11);
      c10 = __reduce_add_sync(F, c10);
      c01 = __reduce_add_sync(F, c01);
      if (lane == 0) {
        s->cnt_n1[rr] = (float)n1;
        s->cnt11[rr]  = (float)c11;
        s->cnt10[rr]  = (float)c10;
        s->cnt01[rr]  = (float)c01;
      }
    }
  }

  __syncthreads();

  // ---- fused GEMM ----
  // row = lane&15 (both half-warps cover the same 16 rows); jgroup g = 2w + (lane>>4).
  // Warps 0..3 -> g 0..7 (unary j 0..63); warps 4..7 -> g 8..15 (pairwise j 0..63).
  // hs reads: quarter-warp lanes hit all 32 banks (WPAD=132) -> conflict-free.
  // Wc reads: warp-uniform per half-warp -> 2-address broadcast, conflict-free.
  const int row   = lane & 15;
  const int g     = (w << 1) + (lane >> 4);
  const int jbase = g * JPW;           // row offset into Wc
  unsigned long long acc2[JPW];
#pragma unroll
  for (int jj = 0; jj < JPW; jj++) acc2[jj] = 0ull;
  const float* hrow  = s->hs[row];
  const float* wbase = s->Wc[jbase];
#pragma unroll 2
  for (int k = 0; k < DIMH; k += 4) {
    ulonglong2 hv = *reinterpret_cast<const ulonglong2*>(hrow + k);   // 4 h values
#pragma unroll
    for (int jj = 0; jj < JPW; jj++) {
      ulonglong2 wv = *reinterpret_cast<const ulonglong2*>(wbase + jj * WPAD + k);
      asm("fma.rn.f32x2 %0, %1, %2, %0;" : "+l"(acc2[jj]) : "l"(hv.x), "l"(wv.x));
      asm("fma.rn.f32x2 %0, %1, %2, %0;" : "+l"(acc2[jj]) : "l"(hv.y), "l"(wv.y));
    }
  }

  // ---- epilogue: binary-u collapse to 2 (unary) / 4 (pairwise) gelu variants ----
  float n1  = s->cnt_n1[row];
  float c01 = s->cnt01[row];
  float c10 = s->cnt10[row];
  float c11 = s->cnt11[row];
  float val;
  if (w < NWARP / 2) {                  // unary: g in 0..7, j = jbase+jj
    float g0 = 0.f, g1 = 0.f;
#pragma unroll
    for (int jj = 0; jj < JPW; jj++) {
      int j = jbase + jj;
      float lo, hi;
      asm("mov.b64 {%0, %1}, %2;" : "=f"(lo), "=f"(hi) : "l"(acc2[jj]));
      float base = lo + hi + s->b1u[j];
      float w2 = s->W2u[j];
      g0 += w2 * gelu_f(base);
      g1 += w2 * gelu_f(base + s->cu[j]);
    }
    val = (256.0f - n1) * g0 + n1 * g1;
  } else {                              // pairwise: g in 8..15, j = jbase-64+jj
    float p00 = 0.f, p01 = 0.f, p10 = 0.f, p11 = 0.f;
#pragma unroll
    for (int jj = 0; jj < JPW; jj++) {
      int j = jbase - HID + jj;
      float lo, hi;
      asm("mov.b64 {%0, %1}, %2;" : "=f"(lo), "=f"(hi) : "l"(acc2[jj]));
      float base = lo + hi + s->b1p[j];
      float A  = s->cp0[j];   // multiplies u_i
      float Bv = s->cp1[j];   // multiplies u_{i+1}
      float w2 = s->W2p[j];
      p00 += w2 * gelu_f(base);
      p01 += w2 * gelu_f(base + Bv);
      p10 += w2 * gelu_f(base + A);
      p11 += w2 * gelu_f(base + A + Bv);
    }
    float c00 = 255.0f - c01 - c10 - c11;
    val = c00 * p00 + c01 * p01 + c10 * p10 + c11 * p11;
  }
  s->partial[g][row] = val;
  __syncthreads();

  if (w == 0 && lane < ROWS) {
    float e = 0.f;
#pragma unroll
    for (int gg = 0; gg < NG; gg++) e += s->partial[gg][lane];
    e += 256.0f * b2u[0] + 255.0f * b2p[0];
    out[r0 + lane] = e;
  }
}

extern "C" void kernel_launch(void* const* d_in, const int* in_sizes, int n_in,
                              void* d_out, int out_size) {
  const float* u   = (const float*)d_in[0];
  const float* h   = (const float*)d_in[1];
  const float* W1u = (const float*)d_in[2];
  const float* b1u = (const float*)d_in[3];
  const float* W2u = (const float*)d_in[4];
  const float* b2u = (const float*)d_in[5];
  const float* W1p = (const float*)d_in[6];
  const float* b1p = (const float*)d_in[7];
  const float* W2p = (const float*)d_in[8];
  const float* b2p = (const float*)d_in[9];
  float* out = (float*)d_out;

  int B    = in_sizes[1] / DIMH;   // 4096
  int grid = B / ROWS;             // 256 blocks -> 2 CTAs/SM, all 148 SMs busy
  size_t smem = sizeof(Smem);      // ~77 KB -> needs opt-in; 2 CTAs fit in 228 KB
  cudaFuncSetAttribute(fem_kernel, cudaFuncAttributeMaxDynamicSharedMemorySize, (int)smem);
  fem_kernel<<<grid, THREADS, smem>>>(u, h, W1u, b1u, W2u, b2u, W1p, b1p, W2p, b2p, out);
}